// round 1
// baseline (speedup 1.0000x reference)
#include <cuda_runtime.h>

// Problem constants
#define BB   64
#define CC   3
#define HH   224
#define PP   8
#define GG   28            // H/P
#define MM   50176         // B*28*28
#define NN   768
#define KWRD 48            // K = 192 bytes = 48 int words

// ---------------- device scratch (no allocations allowed) ----------------
__device__ unsigned g_amax_x;
__device__ unsigned g_amax_w;
__device__ int4 g_xq[MM * KWRD / 4];    // [M][48] ints, GEMM-ready A (int8 packed)
__device__ int4 g_wqT[KWRD * NN / 4];   // [48][768] ints, k-major B (int8 packed)

// ---------------- kernels ----------------
__global__ void k_init() {
    g_amax_x = 0u;
    g_amax_w = 0u;
}

__global__ void k_absmax(const float4* __restrict__ p, int n4, int which) {
    float m = 0.f;
    for (int i = blockIdx.x * blockDim.x + threadIdx.x; i < n4; i += gridDim.x * blockDim.x) {
        float4 v = p[i];
        m = fmaxf(m, fmaxf(fmaxf(fabsf(v.x), fabsf(v.y)), fmaxf(fabsf(v.z), fabsf(v.w))));
    }
    #pragma unroll
    for (int o = 16; o; o >>= 1) m = fmaxf(m, __shfl_xor_sync(0xffffffffu, m, o));
    __shared__ float sm[8];
    if ((threadIdx.x & 31) == 0) sm[threadIdx.x >> 5] = m;
    __syncthreads();
    if (threadIdx.x < 32) {
        m = (threadIdx.x < 8) ? sm[threadIdx.x] : 0.f;
        #pragma unroll
        for (int o = 4; o; o >>= 1) m = fmaxf(m, __shfl_xor_sync(0xffffffffu, m, o));
        if (threadIdx.x == 0)
            atomicMax(which ? &g_amax_w : &g_amax_x, __float_as_uint(m));
    }
}

__device__ __forceinline__ int quant1(float v, float s) {
    float t = v / s;                       // IEEE div to match reference x/s
    t = fminf(fmaxf(t, -127.f), 127.f);
    return __float2int_rn(t);              // round-to-nearest-even == jnp.round
}

// Quantize x and scatter into GEMM A layout: g_xq[m][k] (one int word = 4 int8 along K)
__global__ void k_quant_x(const float* __restrict__ x) {
    int idx = blockIdx.x * blockDim.x + threadIdx.x;
    if (idx >= MM * KWRD) return;
    float s = fmaxf(__uint_as_float(g_amax_x), 1e-8f) / 127.f;
    int m = idx / KWRD, k = idx - m * KWRD;
    int b = m / 784, r = m - b * 784;
    int gx = r / 28, gy = r - gx * 28;
    int c = k >> 4, pq = k & 15, pr = pq >> 1, hf = pq & 1;
    const float4 v = *(const float4*)(x + ((((b * 3 + c) * 224) + gx * 8 + pr) * 224 + gy * 8 + hf * 4));
    int i0 = quant1(v.x, s), i1 = quant1(v.y, s), i2 = quant1(v.z, s), i3 = quant1(v.w, s);
    ((int*)g_xq)[idx] = (i0 & 0xff) | ((i1 & 0xff) << 8) | ((i2 & 0xff) << 16) | ((i3 & 0xff) << 24);
}

// Quantize w into k-major layout: g_wqT[k][col], col = output channel d
__global__ void k_quant_w(const float* __restrict__ w) {
    int idx = blockIdx.x * blockDim.x + threadIdx.x;
    if (idx >= KWRD * NN) return;
    float s = fmaxf(__uint_as_float(g_amax_w), 1e-8f) / 127.f;
    int k = idx / NN, col = idx - k * NN;
    const float4 v = *(const float4*)(w + col * 192 + k * 4);
    int i0 = quant1(v.x, s), i1 = quant1(v.y, s), i2 = quant1(v.z, s), i3 = quant1(v.w, s);
    ((int*)g_wqT)[idx] = (i0 & 0xff) | ((i1 & 0xff) << 8) | ((i2 & 0xff) << 16) | ((i3 & 0xff) << 24);
}

// dp4a GEMM: C[M][N] = A[M][192]i8 * B[192][N]i8 (int32 exact) * (sx*sw) + bias
// CTA: 64 rows x 128 cols, 256 threads (16x16), thread tile 4x8. Full K resident.
__global__ void __launch_bounds__(256) k_gemm(const float* __restrict__ bias,
                                              float* __restrict__ out) {
    __shared__ int4 sA[64 * 12];   // [m][k4]  : 12 int4 per row (48 int words)
    __shared__ int4 sB[48 * 32];   // [k][col4]: 32 int4 per k (128 cols)

    const int t  = threadIdx.x;
    const int m0 = blockIdx.x * 64;
    const int n0 = blockIdx.y * 128;

    // A: source layout == dest layout -> fully linear, coalesced, conflict-free
    const int4* gA = g_xq + m0 * 12;
    #pragma unroll
    for (int i = t; i < 768; i += 256) sA[i] = gA[i];
    // B: [48][768] global -> [48][128] slice, linear per k-row, coalesced
    #pragma unroll
    for (int i = t; i < 1536; i += 256) {
        int k = i >> 5, cv = i & 31;
        sB[i] = g_wqT[k * 192 + (n0 >> 2) + cv];
    }
    __syncthreads();

    const int tx = t & 15, ty = t >> 4;
    const int rowb = ty * 4;

    int acc[4][8];
    #pragma unroll
    for (int r = 0; r < 4; r++)
        #pragma unroll
        for (int j = 0; j < 8; j++) acc[r][j] = 0;

    #pragma unroll
    for (int k4 = 0; k4 < 12; k4++) {
        int4 a0 = sA[(rowb + 0) * 12 + k4];
        int4 a1 = sA[(rowb + 1) * 12 + k4];
        int4 a2 = sA[(rowb + 2) * 12 + k4];
        int4 a3 = sA[(rowb + 3) * 12 + k4];
        const int* ap0 = (const int*)&a0;
        const int* ap1 = (const int*)&a1;
        const int* ap2 = (const int*)&a2;
        const int* ap3 = (const int*)&a3;
        #pragma unroll
        for (int kk = 0; kk < 4; kk++) {
            int4 b0 = sB[(k4 * 4 + kk) * 32 + tx * 2];
            int4 b1 = sB[(k4 * 4 + kk) * 32 + tx * 2 + 1];
            int bw[8] = {b0.x, b0.y, b0.z, b0.w, b1.x, b1.y, b1.z, b1.w};
            int aw[4] = {ap0[kk], ap1[kk], ap2[kk], ap3[kk]};
            #pragma unroll
            for (int r = 0; r < 4; r++)
                #pragma unroll
                for (int j = 0; j < 8; j++)
                    acc[r][j] = __dp4a(aw[r], bw[j], acc[r][j]);
        }
    }

    const float sx = fmaxf(__uint_as_float(g_amax_x), 1e-8f) / 127.f;
    const float sw = fmaxf(__uint_as_float(g_amax_w), 1e-8f) / 127.f;
    const float sc = sx * sw;

    const int col0 = n0 + tx * 8;
    const float4 bLo = *(const float4*)(bias + col0);
    const float4 bHi = *(const float4*)(bias + col0 + 4);

    #pragma unroll
    for (int r = 0; r < 4; r++) {
        float* o = out + (size_t)(m0 + rowb + r) * NN + col0;
        float4 v0, v1;
        v0.x = (float)acc[r][0] * sc + bLo.x;
        v0.y = (float)acc[r][1] * sc + bLo.y;
        v0.z = (float)acc[r][2] * sc + bLo.z;
        v0.w = (float)acc[r][3] * sc + bLo.w;
        v1.x = (float)acc[r][4] * sc + bHi.x;
        v1.y = (float)acc[r][5] * sc + bHi.y;
        v1.z = (float)acc[r][6] * sc + bHi.z;
        v1.w = (float)acc[r][7] * sc + bHi.w;
        *(float4*)o       = v0;
        *(float4*)(o + 4) = v1;
    }
}

// ---------------- launch ----------------
extern "C" void kernel_launch(void* const* d_in, const int* in_sizes, int n_in,
                              void* d_out, int out_size) {
    const float* x = (const float*)d_in[0];   // [64,3,224,224]
    const float* w = (const float*)d_in[1];   // [768,3,8,8]
    const float* b = (const float*)d_in[2];   // [768]
    float* out = (float*)d_out;               // [64,784,768]

    k_init<<<1, 1>>>();
    k_absmax<<<1024, 256>>>((const float4*)x, (BB * CC * HH * HH) / 4, 0);
    k_absmax<<<72, 256>>>((const float4*)w, (NN * 192) / 4, 1);
    k_quant_x<<<(MM * KWRD + 255) / 256, 256>>>(x);
    k_quant_w<<<(KWRD * NN + 255) / 256, 256>>>(w);
    dim3 grid(MM / 64, NN / 128);
    k_gemm<<<grid, 256>>>(b, out);
}

// round 3
// speedup vs baseline: 1.2501x; 1.2501x over previous
#include <cuda_runtime.h>
#include <cstdint>

// Problem constants
#define BB   64
#define MM   50176         // B*28*28
#define NN   768
#define KK   192           // 3*8*8
#define KWRD 48            // K in int words (4 int8 each)

// ---------------- device scratch (no allocations allowed) ----------------
__device__ unsigned g_amax_x;
__device__ unsigned g_amax_w;
__device__ int4 g_xq[MM * KWRD / 4];    // [M][48] words: A, row-major k
__device__ int4 g_wq[NN * KWRD / 4];    // [N][48] words: B, n-major rows of k (natural w layout)

// ---------------- small kernels ----------------
__global__ void k_init() { g_amax_x = 0u; g_amax_w = 0u; }

// blockIdx.y == 0 -> x tensor, 1 -> w tensor
__global__ void k_absmax(const float4* __restrict__ px, int nx4,
                         const float4* __restrict__ pw, int nw4) {
    const float4* p = blockIdx.y ? pw : px;
    const int n4 = blockIdx.y ? nw4 : nx4;
    float m = 0.f;
    for (int i = blockIdx.x * blockDim.x + threadIdx.x; i < n4; i += gridDim.x * blockDim.x) {
        float4 v = p[i];
        m = fmaxf(m, fmaxf(fmaxf(fabsf(v.x), fabsf(v.y)), fmaxf(fabsf(v.z), fabsf(v.w))));
    }
    #pragma unroll
    for (int o = 16; o; o >>= 1) m = fmaxf(m, __shfl_xor_sync(0xffffffffu, m, o));
    __shared__ float sm[8];
    if ((threadIdx.x & 31) == 0) sm[threadIdx.x >> 5] = m;
    __syncthreads();
    if (threadIdx.x < 32) {
        m = (threadIdx.x < 8) ? sm[threadIdx.x] : 0.f;
        #pragma unroll
        for (int o = 4; o; o >>= 1) m = fmaxf(m, __shfl_xor_sync(0xffffffffu, m, o));
        if (threadIdx.x == 0)
            atomicMax(blockIdx.y ? &g_amax_w : &g_amax_x, __float_as_uint(m));
    }
}

__device__ __forceinline__ int quant1(float v, float s) {
    float t = v / s;
    t = fminf(fmaxf(t, -127.f), 127.f);
    return __float2int_rn(t);
}
__device__ __forceinline__ int pack4(float4 v, float s) {
    int i0 = quant1(v.x, s), i1 = quant1(v.y, s), i2 = quant1(v.z, s), i3 = quant1(v.w, s);
    return (i0 & 0xff) | ((i1 & 0xff) << 8) | ((i2 & 0xff) << 16) | ((i3 & 0xff) << 24);
}

// quant x: one block per (b, gx) slab. Coalesced reads, smem transpose, contiguous writes.
__global__ void __launch_bounds__(256) k_quant_x(const float* __restrict__ x) {
    __shared__ int sq[28 * 49];               // [gy][kw], pad 49 -> conflict-free
    const int b = blockIdx.x / 28, gx = blockIdx.x % 28;
    const float s = fmaxf(__uint_as_float(g_amax_x), 1e-8f) / 127.f;
    const int t = threadIdx.x;

    // 24 rows (c,pr) x 224 floats, read as float4 (56 per row)
    for (int i = t; i < 1344; i += 256) {
        int row = i / 56, pos = i - row * 56;        // row = c*8+pr
        int c = row >> 3, pr = row & 7;
        float4 v = *(const float4*)(x + (((b * 3 + c) * 224 + gx * 8 + pr) * 224) + pos * 4);
        int gy = pos >> 1, hf = pos & 1;
        sq[gy * 49 + c * 16 + pr * 2 + hf] = pack4(v, s);
    }
    __syncthreads();
    const int m0 = b * 784 + gx * 28;
    int* dst = (int*)g_xq + (size_t)m0 * 48;
    for (int i = t; i < 1344; i += 256) {
        int gy = i / 48, kw = i - gy * 48;
        dst[i] = sq[gy * 49 + kw];
    }
}

// quant w into natural [n][k] layout: fully linear
__global__ void k_quant_w(const float* __restrict__ w) {
    int idx = blockIdx.x * blockDim.x + threadIdx.x;
    if (idx >= NN * KWRD) return;
    float s = fmaxf(__uint_as_float(g_amax_w), 1e-8f) / 127.f;
    ((int*)g_wq)[idx] = pack4(((const float4*)w)[idx], s);
}

// ---------------- IMMA GEMM ----------------
__device__ __forceinline__ void ldsm4(uint32_t& r0, uint32_t& r1, uint32_t& r2, uint32_t& r3,
                                      uint32_t addr) {
    asm volatile("ldmatrix.sync.aligned.m8n8.x4.shared.b16 {%0,%1,%2,%3}, [%4];"
                 : "=r"(r0), "=r"(r1), "=r"(r2), "=r"(r3) : "r"(addr));
}
__device__ __forceinline__ void imma(int* c, uint32_t a0, uint32_t a1, uint32_t a2, uint32_t a3,
                                     uint32_t b0, uint32_t b1) {
    asm volatile(
        "mma.sync.aligned.m16n8k32.row.col.s32.s8.s8.s32 "
        "{%0,%1,%2,%3}, {%4,%5,%6,%7}, {%8,%9}, {%0,%1,%2,%3};"
        : "+r"(c[0]), "+r"(c[1]), "+r"(c[2]), "+r"(c[3])
        : "r"(a0), "r"(a1), "r"(a2), "r"(a3), "r"(b0), "r"(b1));
}

#define A_STRIDE 208           // 192 data + 16 pad
#define SA_BYTES (64 * A_STRIDE)
#define SB_BYTES (128 * A_STRIDE)

// CTA 64(M) x 128(N), 256 thr = 8 warps of 32x32. Full K=192 resident.
__global__ void __launch_bounds__(256) k_gemm(const float* __restrict__ bias,
                                              float* __restrict__ out) {
    __shared__ __align__(16) char smem[SA_BYTES + SB_BYTES];
    const int t = threadIdx.x;
    const int m0 = blockIdx.x * 64;
    const int n0 = blockIdx.y * 128;

    // load tiles (linear, coalesced)
    {
        const int4* gA = g_xq + (size_t)m0 * 12;
        #pragma unroll
        for (int i = t; i < 64 * 12; i += 256) {
            int row = i / 12, kv = i - row * 12;
            *(int4*)(smem + row * A_STRIDE + kv * 16) = gA[i];
        }
        const int4* gB = g_wq + (size_t)n0 * 12;
        #pragma unroll
        for (int i = t; i < 128 * 12; i += 256) {
            int row = i / 12, kv = i - row * 12;
            *(int4*)(smem + SA_BYTES + row * A_STRIDE + kv * 16) = gB[i];
        }
    }
    __syncthreads();

    const int warp = t >> 5, lane = t & 31;
    const int wm = warp >> 2, wn = warp & 3;       // warp tile: rows wm*32, cols wn*32
    const int quad = lane >> 3, li = lane & 7;
    const uint32_t sbase = (uint32_t)__cvta_generic_to_shared(smem);

    // ldmatrix lane addresses (offset by kf*32 in loop)
    const int rsel = ((quad & 1) << 3) + li;       // row within 16-row fragment
    const int osel = (quad >> 1) << 4;             // 0 or 16 bytes
    uint32_t aAddr0 = sbase + (wm * 32 + rsel) * A_STRIDE + osel;
    uint32_t aAddr1 = aAddr0 + 16 * A_STRIDE;
    uint32_t bAddr0 = sbase + SA_BYTES + (wn * 32 + rsel) * A_STRIDE + osel;
    uint32_t bAddr1 = bAddr0 + 16 * A_STRIDE;

    int acc[2][4][4];
    #pragma unroll
    for (int mi = 0; mi < 2; mi++)
        #pragma unroll
        for (int f = 0; f < 4; f++)
            #pragma unroll
            for (int j = 0; j < 4; j++) acc[mi][f][j] = 0;

    #pragma unroll
    for (int kf = 0; kf < 6; kf++) {
        const uint32_t ko = kf * 32;
        uint32_t a0[4], a1[4], p0[4], p1[4];
        ldsm4(a0[0], a0[1], a0[2], a0[3], aAddr0 + ko);
        ldsm4(a1[0], a1[1], a1[2], a1[3], aAddr1 + ko);
        ldsm4(p0[0], p0[1], p0[2], p0[3], bAddr0 + ko);   // n-frags 0,1
        ldsm4(p1[0], p1[1], p1[2], p1[3], bAddr1 + ko);   // n-frags 2,3
        imma(acc[0][0], a0[0], a0[1], a0[2], a0[3], p0[0], p0[2]);
        imma(acc[0][1], a0[0], a0[1], a0[2], a0[3], p0[1], p0[3]);
        imma(acc[0][2], a0[0], a0[1], a0[2], a0[3], p1[0], p1[2]);
        imma(acc[0][3], a0[0], a0[1], a0[2], a0[3], p1[1], p1[3]);
        imma(acc[1][0], a1[0], a1[1], a1[2], a1[3], p0[0], p0[2]);
        imma(acc[1][1], a1[0], a1[1], a1[2], a1[3], p0[1], p0[3]);
        imma(acc[1][2], a1[0], a1[1], a1[2], a1[3], p1[0], p1[2]);
        imma(acc[1][3], a1[0], a1[1], a1[2], a1[3], p1[1], p1[3]);
    }

    const float sx = fmaxf(__uint_as_float(g_amax_x), 1e-8f) / 127.f;
    const float sw = fmaxf(__uint_as_float(g_amax_w), 1e-8f) / 127.f;
    const float sc = sx * sw;

    const int r = lane >> 2, cp = lane & 3;
    #pragma unroll
    for (int f = 0; f < 4; f++) {
        const int col = n0 + wn * 32 + f * 8 + cp * 2;
        const float2 bv = *(const float2*)(bias + col);
        #pragma unroll
        for (int mi = 0; mi < 2; mi++) {
            const int row0 = m0 + wm * 32 + mi * 16 + r;
            float2 v0, v1;
            v0.x = (float)acc[mi][f][0] * sc + bv.x;
            v0.y = (float)acc[mi][f][1] * sc + bv.y;
            v1.x = (float)acc[mi][f][2] * sc + bv.x;
            v1.y = (float)acc[mi][f][3] * sc + bv.y;
            *(float2*)(out + (size_t)row0 * NN + col)       = v0;
            *(float2*)(out + (size_t)(row0 + 8) * NN + col) = v1;
        }
    }
}

// ---------------- launch ----------------
extern "C" void kernel_launch(void* const* d_in, const int* in_sizes, int n_in,
                              void* d_out, int out_size) {
    const float* x = (const float*)d_in[0];   // [64,3,224,224]
    const float* w = (const float*)d_in[1];   // [768,3,8,8]
    const float* b = (const float*)d_in[2];   // [768]
    float* out = (float*)d_out;               // [64,784,768] fp32

    k_init<<<1, 1>>>();
    dim3 agrid(1024, 2);
    k_absmax<<<agrid, 256>>>((const float4*)x, (BB * 3 * 224 * 224) / 4,
                             (const float4*)w, (NN * KK) / 4);
    k_quant_x<<<BB * 28, 256>>>(x);
    k_quant_w<<<(NN * KWRD + 255) / 256, 256>>>(w);
    dim3 grid(MM / 64, NN / 128);
    k_gemm<<<grid, 256>>>(b, out);
}